// round 12
// baseline (speedup 1.0000x reference)
#include <cuda_runtime.h>
#include <cstdint>

// Convex_f: out[b,j,k] = (interior && Dy>0) ? 0.5*(y[j-1]+y[j+1]) - param[j]
//                                          : y[j] - param[j]   // bit-exact vs reference ((x+p)-p)
// where y = x + param, Dy = 2*y[j] - y[j-1] - y[j+1].
// Shapes: B=256, N=8192, K=16, float32, contiguous (B,N,K).
//
// R12: persistent blocks + 2-stage cp.async double buffer. While computing
// tile t from stage s, copies for tile t+stride stream into stage s^1 —
// DRAM requests flow continuously through compute phases instead of in
// per-block bursts. Stage tile = 128 j-rows; smem 33.3KB -> 6 blocks/SM.

constexpr int Bn = 256;
constexpr int Nn = 8192;
constexpr int KV = 4;                   // float4 per (b,j) row
constexpr int TJ = 128;                 // j-rows per tile
constexpr int TPB_N = Nn / TJ;          // 64 tiles per batch
constexpr int TILES = Bn * TPB_N;       // 16384
constexpr int CB = 256;
constexpr int EPT = (TJ * KV) / CB;     // 2 float4 per thread per tile
constexpr int SROWS = (TJ + 2) * KV;    // 520 float4 incl. halo rows
constexpr int NBLK = 148 * 6;           // persistent grid = one full wave

__device__ __forceinline__ void cp_async16(uint32_t smem_addr, const void* gptr) {
    asm volatile("cp.async.cg.shared.global [%0], [%1], 16;\n"
                 :: "r"(smem_addr), "l"(gptr));
}

__global__ __launch_bounds__(CB, 6)
void convex_kernel(const float4* __restrict__ x4,
                   const float4* __restrict__ p4,
                   float4* __restrict__ o4)
{
    __shared__ float4 xs[2][SROWS];
    __shared__ float4 ps[2][SROWS];

    int tid = threadIdx.x;
    uint32_t xs0 = (uint32_t)__cvta_generic_to_shared(&xs[0][0]);
    uint32_t ps0 = (uint32_t)__cvta_generic_to_shared(&ps[0][0]);

    // ---- copy issue for one tile into stage st (all threads participate) ----
    auto issue_tile = [&](int t, int st) {
        int b    = t >> 6;                       // t / TPB_N
        int jt   = (t & (TPB_N - 1)) * TJ;
        int base = b * (Nn * KV) + jt * KV;
        uint32_t xsb = xs0 + (uint32_t)st * SROWS * 16;
        uint32_t psb = ps0 + (uint32_t)st * SROWS * 16;
        #pragma unroll
        for (int r = 0; r < EPT; r++) {
            int flat = r * CB + tid;             // j_local*KV + kv
            cp_async16(xsb + (flat + KV) * 16, &x4[base + flat]);
            cp_async16(psb + (flat + KV) * 16, &p4[base + flat]);
        }
        // halo rows j_local = -1 and TJ for both arrays (clamped at edges;
        // clamped values are never consumed — those j are non-interior).
        if (tid < 4 * KV) {
            int kvh  = tid & (KV - 1);
            int sel  = tid >> 2;                 // 0:x lo, 1:x hi, 2:p lo, 3:p hi
            bool hi  = sel & 1;
            bool isp = sel >= 2;
            int jg   = hi ? (jt + TJ) : (jt - 1);
            jg = (jg < 0) ? 0 : ((jg > Nn - 1) ? (Nn - 1) : jg);
            int offh = b * (Nn * KV) + jg * KV + kvh;
            int slot = hi ? ((TJ + 1) * KV + kvh) : kvh;
            if (isp) cp_async16(psb + slot * 16, &p4[offh]);
            else     cp_async16(xsb + slot * 16, &x4[offh]);
        }
        asm volatile("cp.async.commit_group;\n");
    };

    int t0 = blockIdx.x;
    if (t0 >= TILES) return;                     // (never true: NBLK < TILES)

    issue_tile(t0, 0);

    int s = 0;
    for (int t = t0; t < TILES; t += NBLK) {
        int tn = t + NBLK;
        bool more = (tn < TILES);
        if (more) issue_tile(tn, s ^ 1);

        if (more) asm volatile("cp.async.wait_group 1;\n" ::: "memory");
        else      asm volatile("cp.async.wait_group 0;\n" ::: "memory");
        __syncthreads();

        // ---- compute tile t from stage s ----
        int b    = t >> 6;
        int jt   = (t & (TPB_N - 1)) * TJ;
        int base = b * (Nn * KV) + jt * KV;
        const float4* xsb = xs[s];
        const float4* psb = ps[s];

        #pragma unroll
        for (int r = 0; r < EPT; r++) {
            int flat = r * CB + tid;
            int j    = jt + (flat >> 2);

            float4 xmv = xsb[flat];            float4 pmv = psb[flat];            // j-1
            float4 x0v = xsb[flat + KV];       float4 p0  = psb[flat + KV];       // j
            float4 xpv = xsb[flat + 2 * KV];   float4 ppv = psb[flat + 2 * KV];   // j+1

            bool interior = (j > 0) && (j < Nn - 1);

            float4 out;
            {
                float ym = xmv.x + pmv.x, y0 = x0v.x + p0.x, yp = xpv.x + ppv.x;
                float sm2  = ym + yp;
                float Dy   = fmaf(2.0f, y0, -sm2);
                float alt  = fmaf(0.5f, sm2, -p0.x);
                float keep = y0 - p0.x;
                out.x = (interior && Dy > 0.0f) ? alt : keep;
            }
            {
                float ym = xmv.y + pmv.y, y0 = x0v.y + p0.y, yp = xpv.y + ppv.y;
                float sm2  = ym + yp;
                float Dy   = fmaf(2.0f, y0, -sm2);
                float alt  = fmaf(0.5f, sm2, -p0.y);
                float keep = y0 - p0.y;
                out.y = (interior && Dy > 0.0f) ? alt : keep;
            }
            {
                float ym = xmv.z + pmv.z, y0 = x0v.z + p0.z, yp = xpv.z + ppv.z;
                float sm2  = ym + yp;
                float Dy   = fmaf(2.0f, y0, -sm2);
                float alt  = fmaf(0.5f, sm2, -p0.z);
                float keep = y0 - p0.z;
                out.z = (interior && Dy > 0.0f) ? alt : keep;
            }
            {
                float ym = xmv.w + pmv.w, y0 = x0v.w + p0.w, yp = xpv.w + ppv.w;
                float sm2  = ym + yp;
                float Dy   = fmaf(2.0f, y0, -sm2);
                float alt  = fmaf(0.5f, sm2, -p0.w);
                float keep = y0 - p0.w;
                out.w = (interior && Dy > 0.0f) ? alt : keep;
            }

            o4[base + flat] = out;
        }

        __syncthreads();   // all reads of stage s done before it is refilled
        s ^= 1;
    }
}

extern "C" void kernel_launch(void* const* d_in, const int* in_sizes, int n_in,
                              void* d_out, int out_size)
{
    const float4* x4 = (const float4*)d_in[0];
    const float4* p4 = (const float4*)d_in[1];
    float4* o4 = (float4*)d_out;

    convex_kernel<<<NBLK, CB>>>(x4, p4, o4);
}

// round 13
// speedup vs baseline: 1.2303x; 1.2303x over previous
#include <cuda_runtime.h>

// Convex_f: out[b,j,k] = (interior && Dy>0) ? 0.5*(y[j-1]+y[j+1]) - param[j]
//                                          : y[j] - param[j]   // bit-exact vs reference ((x+p)-p)
// where y = x + param, Dy = 2*y[j] - y[j-1] - y[j+1].
// Shapes: B=256, N=8192, K=16, float32, contiguous (B,N,K).
//
// R13 = R8 shape at half block size. Same proven recipe: 8 front-batched
// LDG.128 per thread, y published to smem, y0/p0 kept in regs. CB=128/TJ=128
// gives 10 independent blocks/SM (vs 5) so load bursts and barriers of
// different blocks interleave finely -> fewer request-supply dead windows.

constexpr int Bn = 256;
constexpr int Nn = 8192;
constexpr int KV = 4;                 // float4 per (b,j) row
constexpr int TJ = 128;               // j-rows per block tile
constexpr int TILES_PER_B = Nn / TJ;  // 64
constexpr int CB = 128;               // threads per block
constexpr int EPT = (TJ * KV) / CB;   // float4 elements per thread = 4

__global__ __launch_bounds__(CB, 10)  // reg cap 51 -> full 8-load batch preserved
void convex_kernel(const float4* __restrict__ x4,
                   const float4* __restrict__ p4,
                   float4* __restrict__ o4)
{
    // y tile with one halo row each side: row jl stored at (jl+1)
    __shared__ float4 ys[(TJ + 2) * KV];

    int tile = blockIdx.x;
    int b    = tile >> 6;                  // tile / TILES_PER_B
    int jt   = (tile & (TILES_PER_B - 1)) * TJ;
    int base = b * (Nn * KV) + jt * KV;    // float4 offset of (b, jt, k=0)
    int tid  = threadIdx.x;

    // ---- Load phase: 8 coalesced LDG.128 per thread, front-batched ----
    float4 pr[EPT];
    float4 yr[EPT];
    #pragma unroll
    for (int r = 0; r < EPT; r++) {
        int flat = r * CB + tid;           // = j_local*KV + kv
        float4 xv = x4[base + flat];
        float4 pv = p4[base + flat];
        pr[r] = pv;
        yr[r] = make_float4(xv.x + pv.x, xv.y + pv.y, xv.z + pv.z, xv.w + pv.w);
    }

    // Halo rows: j_local = -1 and j_local = TJ (clamped at global edges;
    // clamped values are never consumed because those j are non-interior).
    if (tid < 2 * KV) {
        int kvh = tid & (KV - 1);
        bool hi = tid >= KV;
        int jg  = hi ? (jt + TJ) : (jt - 1);
        jg = (jg < 0) ? 0 : ((jg > Nn - 1) ? (Nn - 1) : jg);
        int offh = b * (Nn * KV) + jg * KV + kvh;
        float4 xv = x4[offh];
        float4 pv = p4[offh];
        int slot = hi ? ((TJ + 1) * KV + kvh) : kvh;
        ys[slot] = make_float4(xv.x + pv.x, xv.y + pv.y, xv.z + pv.z, xv.w + pv.w);
    }

    #pragma unroll
    for (int r = 0; r < EPT; r++) {
        int flat = r * CB + tid;
        ys[flat + KV] = yr[r];             // row jl stored at (jl+1)
    }

    __syncthreads();

    // ---- Compute phase: neighbors from smem, y0/p0 from regs ----
    #pragma unroll
    for (int r = 0; r < EPT; r++) {
        int flat = r * CB + tid;
        int j    = jt + (flat >> 2);       // global j
        float4 y0 = yr[r];
        float4 p0 = pr[r];
        float4 ym = ys[flat];              // j-1
        float4 yp = ys[flat + 2 * KV];     // j+1

        bool interior = (j > 0) && (j < Nn - 1);

        float4 out;
        {
            float s    = ym.x + yp.x;
            float Dy   = fmaf(2.0f, y0.x, -s);
            float alt  = fmaf(0.5f, s, -p0.x);
            float keep = y0.x - p0.x;
            out.x = (interior && Dy > 0.0f) ? alt : keep;
        }
        {
            float s    = ym.y + yp.y;
            float Dy   = fmaf(2.0f, y0.y, -s);
            float alt  = fmaf(0.5f, s, -p0.y);
            float keep = y0.y - p0.y;
            out.y = (interior && Dy > 0.0f) ? alt : keep;
        }
        {
            float s    = ym.z + yp.z;
            float Dy   = fmaf(2.0f, y0.z, -s);
            float alt  = fmaf(0.5f, s, -p0.z);
            float keep = y0.z - p0.z;
            out.z = (interior && Dy > 0.0f) ? alt : keep;
        }
        {
            float s    = ym.w + yp.w;
            float Dy   = fmaf(2.0f, y0.w, -s);
            float alt  = fmaf(0.5f, s, -p0.w);
            float keep = y0.w - p0.w;
            out.w = (interior && Dy > 0.0f) ? alt : keep;
        }

        o4[base + flat] = out;
    }
}

extern "C" void kernel_launch(void* const* d_in, const int* in_sizes, int n_in,
                              void* d_out, int out_size)
{
    const float4* x4 = (const float4*)d_in[0];
    const float4* p4 = (const float4*)d_in[1];
    float4* o4 = (float4*)d_out;

    int blocks = Bn * TILES_PER_B;        // 16384
    convex_kernel<<<blocks, CB>>>(x4, p4, o4);
}